// round 2
// baseline (speedup 1.0000x reference)
#include <cuda_runtime.h>

#define N_NODES 50000
#define N_EDGES 1600000
#define BATCH   4
#define T_STEPS 50
#define DT      0.02f

// ---------------- static scratch (no allocations allowed) ----------------
__device__ int    g_hist[N_NODES];
__device__ int    g_row_start[N_NODES + 1];
__device__ int    g_cursor[N_NODES];
__device__ int    g_col[N_EDGES];
__device__ float  g_w[N_EDGES];
__device__ float4 g_rates[2][N_NODES];   // ping-pong rate buffers, [node] = 4 batches
__device__ float4 g_v[N_NODES];          // membrane state, 4 batches per node
__device__ float  g_alpha[N_NODES];

// ---------------- preprocessing ----------------

// Zero histogram, init state v0 = bias, rates0 = relu(bias), alpha = DT/max(tau,DT)
__global__ void init_kernel(const float* __restrict__ bias,
                            const float* __restrict__ tau) {
    int n = blockIdx.x * blockDim.x + threadIdx.x;
    if (n >= N_NODES) return;
    g_hist[n] = 0;
    float b = bias[n];
    g_v[n] = make_float4(b, b, b, b);
    float r = fmaxf(b, 0.0f);
    g_rates[0][n] = make_float4(r, r, r, r);
    float tt = fmaxf(tau[n], DT);
    g_alpha[n] = DT / tt;
}

__global__ void hist_kernel(const int* __restrict__ tgt) {
    int e = blockIdx.x * blockDim.x + threadIdx.x;
    if (e >= N_EDGES) return;
    atomicAdd(&g_hist[tgt[e]], 1);
}

// Single-block exclusive scan over 50K histogram entries -> row_start + cursor
__global__ void scan_kernel() {
    __shared__ int s[1024];
    int tid = threadIdx.x;
    const int chunk = (N_NODES + 1023) / 1024;   // 49
    int beg = tid * chunk;
    int end = min(beg + chunk, N_NODES);
    int sum = 0;
    for (int i = beg; i < end; i++) sum += g_hist[i];
    s[tid] = sum;
    __syncthreads();
    // inclusive Hillis-Steele over the 1024 partial sums
    for (int off = 1; off < 1024; off <<= 1) {
        int v = (tid >= off) ? s[tid - off] : 0;
        __syncthreads();
        s[tid] += v;
        __syncthreads();
    }
    int prefix = (tid > 0) ? s[tid - 1] : 0;
    for (int i = beg; i < end; i++) {
        g_row_start[i] = prefix;
        g_cursor[i]    = prefix;
        prefix += g_hist[i];
    }
    if (tid == 0) g_row_start[N_NODES] = s[1023];
}

// Counting-sort edges into CSR (by target), computing weights inline.
__global__ void scatter_kernel(const int*   __restrict__ src,
                               const int*   __restrict__ tgt,
                               const float* __restrict__ sign,
                               const float* __restrict__ cnt,
                               const float* __restrict__ str) {
    int e = blockIdx.x * blockDim.x + threadIdx.x;
    if (e >= N_EDGES) return;
    float w = sign[e] * fmaxf(cnt[e], 0.0f) * fmaxf(str[e], 0.0f);
    int pos = atomicAdd(&g_cursor[tgt[e]], 1);
    g_col[pos] = src[e];
    g_w[pos]   = w;
}

// ---------------- hot loop: one kernel per timestep ----------------
// Warp-per-row segmented SpMV (batch vectorized in float4) + fused Euler update.
__global__ void __launch_bounds__(256)
step_kernel(const float* __restrict__ x,
            float*       __restrict__ out,
            const float* __restrict__ bias,
            int t, int parity) {
    int gw   = (blockIdx.x * blockDim.x + threadIdx.x) >> 5;  // row = global warp id
    int lane = threadIdx.x & 31;
    if (gw >= N_NODES) return;

    const float4* __restrict__ rin  = g_rates[parity];
    float4*       __restrict__ rout = g_rates[parity ^ 1];

    int beg = g_row_start[gw];
    int end = g_row_start[gw + 1];

    float4 acc = make_float4(0.f, 0.f, 0.f, 0.f);
    for (int e = beg + lane; e < end; e += 32) {
        float  w = g_w[e];
        float4 r = rin[g_col[e]];
        acc.x = fmaf(w, r.x, acc.x);
        acc.y = fmaf(w, r.y, acc.y);
        acc.z = fmaf(w, r.z, acc.z);
        acc.w = fmaf(w, r.w, acc.w);
    }
#pragma unroll
    for (int off = 16; off; off >>= 1) {
        acc.x += __shfl_down_sync(0xffffffffu, acc.x, off);
        acc.y += __shfl_down_sync(0xffffffffu, acc.y, off);
        acc.z += __shfl_down_sync(0xffffffffu, acc.z, off);
        acc.w += __shfl_down_sync(0xffffffffu, acc.w, off);
    }

    if (lane == 0) {
        float4 vv = g_v[gw];
        float  b  = bias[gw];
        float  a  = g_alpha[gw];
        const long long TN   = (long long)T_STEPS * N_NODES;
        const long long base = (long long)t * N_NODES + gw;

        float4 vn;
        vn.x = vv.x + a * (b + acc.x + x[base          ] - vv.x);
        vn.y = vv.y + a * (b + acc.y + x[base +     TN ] - vv.y);
        vn.z = vv.z + a * (b + acc.z + x[base + 2 * TN ] - vv.z);
        vn.w = vv.w + a * (b + acc.w + x[base + 3 * TN ] - vv.w);
        g_v[gw] = vn;

        float4 r = make_float4(fmaxf(vn.x, 0.f), fmaxf(vn.y, 0.f),
                               fmaxf(vn.z, 0.f), fmaxf(vn.w, 0.f));
        rout[gw] = r;

        out[base          ] = r.x;
        out[base +     TN ] = r.y;
        out[base + 2 * TN ] = r.z;
        out[base + 3 * TN ] = r.w;
    }
}

// ---------------- launch ----------------
extern "C" void kernel_launch(void* const* d_in, const int* in_sizes, int n_in,
                              void* d_out, int out_size) {
    const float* x    = (const float*)d_in[0];
    const float* bias = (const float*)d_in[1];
    const float* tau  = (const float*)d_in[2];
    const float* sign = (const float*)d_in[3];
    const float* cnt  = (const float*)d_in[4];
    const float* str  = (const float*)d_in[5];
    const int*   src  = (const int*)  d_in[6];
    const int*   tgt  = (const int*)  d_in[7];
    float*       out  = (float*)d_out;

    init_kernel<<<(N_NODES + 255) / 256, 256>>>(bias, tau);
    hist_kernel<<<(N_EDGES + 255) / 256, 256>>>(tgt);
    scan_kernel<<<1, 1024>>>();
    scatter_kernel<<<(N_EDGES + 255) / 256, 256>>>(src, tgt, sign, cnt, str);

    // 8 warps per block -> 8 rows per block; 6250 blocks covers 50000 rows exactly
    for (int t = 0; t < T_STEPS; t++) {
        step_kernel<<<N_NODES / 8, 256>>>(x, out, bias, t, t & 1);
    }
}

// round 4
// speedup vs baseline: 1.5293x; 1.5293x over previous
#include <cuda_runtime.h>

#define N_NODES 50000
#define N_EDGES 1600000
#define BATCH   4
#define T_STEPS 50
#define DT      0.02f

// ---------------- static scratch (no allocations allowed) ----------------
__device__ int    g_hist[N_NODES];
__device__ int    g_row_start[N_NODES + 1];
__device__ int    g_cursor[N_NODES];
__device__ int2   g_edges[N_EDGES];       // (src_col, weight-as-int-bits), CSR by target
__device__ float4 g_rates[2][N_NODES];    // ping-pong rate buffers, [node] = 4 batches
__device__ float  g_v[BATCH * N_NODES];   // membrane state, SoA [batch][node]
__device__ float  g_alpha[N_NODES];

// ---------------- preprocessing ----------------

__global__ void init_kernel(const float* __restrict__ bias,
                            const float* __restrict__ tau) {
    int n = blockIdx.x * blockDim.x + threadIdx.x;
    if (n >= N_NODES) return;
    g_hist[n] = 0;
    float b = bias[n];
#pragma unroll
    for (int bb = 0; bb < BATCH; bb++) g_v[bb * N_NODES + n] = b;
    float r = fmaxf(b, 0.0f);
    g_rates[0][n] = make_float4(r, r, r, r);
    float tt = fmaxf(tau[n], DT);
    g_alpha[n] = DT / tt;
}

__global__ void hist_kernel(const int* __restrict__ tgt) {
    int e = blockIdx.x * blockDim.x + threadIdx.x;
    if (e >= N_EDGES) return;
    atomicAdd(&g_hist[tgt[e]], 1);
}

// Single-block exclusive scan over 50K histogram entries -> row_start + cursor
__global__ void scan_kernel() {
    __shared__ int s[1024];
    int tid = threadIdx.x;
    const int chunk = (N_NODES + 1023) / 1024;   // 49
    int beg = tid * chunk;
    int end = min(beg + chunk, N_NODES);
    int sum = 0;
    for (int i = beg; i < end; i++) sum += g_hist[i];
    s[tid] = sum;
    __syncthreads();
    for (int off = 1; off < 1024; off <<= 1) {
        int v = (tid >= off) ? s[tid - off] : 0;
        __syncthreads();
        s[tid] += v;
        __syncthreads();
    }
    int prefix = (tid > 0) ? s[tid - 1] : 0;
    for (int i = beg; i < end; i++) {
        g_row_start[i] = prefix;
        g_cursor[i]    = prefix;
        prefix += g_hist[i];
    }
    if (tid == 0) g_row_start[N_NODES] = s[1023];
}

// Counting-sort edges into CSR (by target), fused (col, weight) record.
__global__ void scatter_kernel(const int*   __restrict__ src,
                               const int*   __restrict__ tgt,
                               const float* __restrict__ sign,
                               const float* __restrict__ cnt,
                               const float* __restrict__ str) {
    int e = blockIdx.x * blockDim.x + threadIdx.x;
    if (e >= N_EDGES) return;
    float w = sign[e] * fmaxf(cnt[e], 0.0f) * fmaxf(str[e], 0.0f);
    int pos = atomicAdd(&g_cursor[tgt[e]], 1);
    g_edges[pos] = make_int2(src[e], __float_as_int(w));
}

// ---------------- hot loop: one kernel per timestep ----------------
// 8 lanes per row (32 rows per 256-thread block), 4-deep unrolled gather for MLP,
// then fully coalesced vectorized epilogue over (batch, row).
__global__ void __launch_bounds__(256)
step_kernel(const float* __restrict__ x,
            float*       __restrict__ out,
            const float* __restrict__ bias,
            int t, int parity) {
    __shared__ float s_acc[BATCH][32];

    int sub = threadIdx.x & 7;        // lane within 8-lane row group
    int grp = threadIdx.x >> 3;       // 0..31 : row group within block
    int row = blockIdx.x * 32 + grp;

    const float4* __restrict__ rin = g_rates[parity];

    float4 acc = make_float4(0.f, 0.f, 0.f, 0.f);
    if (row < N_NODES) {
        int beg = g_row_start[row];
        int end = g_row_start[row + 1];
        for (int e0 = beg; e0 < end; e0 += 32) {
            int2 ed[4];
            bool p[4];
#pragma unroll
            for (int j = 0; j < 4; j++) {
                int ee = e0 + sub + 8 * j;
                p[j]  = ee < end;
                ed[j] = p[j] ? __ldcs(&g_edges[ee]) : make_int2(0, 0);
            }
#pragma unroll
            for (int j = 0; j < 4; j++) {
                if (p[j]) {
                    float4 r = __ldg(&rin[ed[j].x]);
                    float  w = __int_as_float(ed[j].y);
                    acc.x = fmaf(w, r.x, acc.x);
                    acc.y = fmaf(w, r.y, acc.y);
                    acc.z = fmaf(w, r.z, acc.z);
                    acc.w = fmaf(w, r.w, acc.w);
                }
            }
        }
    }
    // reduce within the 8-lane group
#pragma unroll
    for (int off = 4; off; off >>= 1) {
        acc.x += __shfl_down_sync(0xffffffffu, acc.x, off);
        acc.y += __shfl_down_sync(0xffffffffu, acc.y, off);
        acc.z += __shfl_down_sync(0xffffffffu, acc.z, off);
        acc.w += __shfl_down_sync(0xffffffffu, acc.w, off);
    }
    if (sub == 0) {
        s_acc[0][grp] = acc.x;
        s_acc[1][grp] = acc.y;
        s_acc[2][grp] = acc.z;
        s_acc[3][grp] = acc.w;
    }
    __syncthreads();

    // epilogue: 128 threads cover (batch, row) fully coalesced
    if (threadIdx.x < BATCH * 32) {
        int b = threadIdx.x >> 5;     // batch
        int r = threadIdx.x & 31;     // row within block
        int row2 = blockIdx.x * 32 + r;
        if (row2 < N_NODES) {
            float a   = g_alpha[row2];
            float bs  = bias[row2];
            float ab  = s_acc[b][r];
            long long idx = (long long)(b * T_STEPS + t) * N_NODES + row2;
            float xv  = x[idx];
            float v   = g_v[b * N_NODES + row2];
            float vn  = v + a * (bs + ab + xv - v);
            g_v[b * N_NODES + row2] = vn;
            float rl = fmaxf(vn, 0.f);
            // write next-step rate component (float4 array viewed as floats)
            float* routf = (float*)(g_rates[parity ^ 1]);
            routf[row2 * 4 + b] = rl;
            out[idx] = rl;
        }
    }
}

// ---------------- launch ----------------
extern "C" void kernel_launch(void* const* d_in, const int* in_sizes, int n_in,
                              void* d_out, int out_size) {
    const float* x    = (const float*)d_in[0];
    const float* bias = (const float*)d_in[1];
    const float* tau  = (const float*)d_in[2];
    const float* sign = (const float*)d_in[3];
    const float* cnt  = (const float*)d_in[4];
    const float* str  = (const float*)d_in[5];
    const int*   src  = (const int*)  d_in[6];
    const int*   tgt  = (const int*)  d_in[7];
    float*       out  = (float*)d_out;

    init_kernel<<<(N_NODES + 255) / 256, 256>>>(bias, tau);
    hist_kernel<<<(N_EDGES + 255) / 256, 256>>>(tgt);
    scan_kernel<<<1, 1024>>>();
    scatter_kernel<<<(N_EDGES + 255) / 256, 256>>>(src, tgt, sign, cnt, str);

    const int step_blocks = (N_NODES + 31) / 32;   // 1563
    for (int t = 0; t < T_STEPS; t++) {
        step_kernel<<<step_blocks, 256>>>(x, out, bias, t, t & 1);
    }
}